// round 4
// baseline (speedup 1.0000x reference)
#include <cuda_runtime.h>
#include <math_constants.h>

// Problem shape (fixed): B=8, N=M=8192, D=3, fp32, scalar output.
// Exact grid-accelerated nearest neighbor for both Chamfer directions.
#define BB 8
#define PPS 8192                 // points per (batch, side)
#define BPTS (BB * PPS)          // 65536 points per side
#define G 52                     // grid cells per axis
#define CELLS (G * G * G)        // 140608
#define NSEG (BB * 2)            // 16 (batch, side) segments
#define TOTC (NSEG * CELLS)      // 2249728 cells total
#define H 0.25f
#define INV_H 4.0f
#define ORIG 6.5f                // grid covers [-6.5, 6.5); inputs bounded ~|5.2|
#define SCAN_BLOCKS 576          // 576 * 4096 >= TOTC

// Static scratch (no allocations allowed).
__device__ int    g_cnt[TOTC];       // cell counts, then scatter cursors
__device__ int    g_start[TOTC + 1]; // global exclusive scan of counts
__device__ int    g_bsum[1024];      // per-scan-block sums
__device__ float4 g_pts[2 * BPTS];   // cell-sorted points (x,y,z, 0.5*|p|^2)
__device__ float  g_part[512];       // per-block partial sums

__device__ __forceinline__ int cell_of(float x, float y, float z, int seg) {
    int cx = min(max((int)((x + ORIG) * INV_H), 0), G - 1);
    int cy = min(max((int)((y + ORIG) * INV_H), 0), G - 1);
    int cz = min(max((int)((z + ORIG) * INV_H), 0), G - 1);
    return seg * CELLS + (cz * G + cy) * G + cx;
}

// ---- build phase ----------------------------------------------------------
__global__ void zero_kernel() {
    int i = blockIdx.x * 256 + threadIdx.x;
    if (i < TOTC) g_cnt[i] = 0;
}

__global__ void count_kernel(const float* __restrict__ gts,
                             const float* __restrict__ preds) {
    int t = blockIdx.x * 256 + threadIdx.x;            // 0..131071
    int db = t < BPTS ? 0 : 1;
    int pi = t - db * BPTS;
    const float* src = db ? preds : gts;
    float x = src[3 * pi], y = src[3 * pi + 1], z = src[3 * pi + 2];
    int seg = (pi >> 13) * 2 + db;
    atomicAdd(&g_cnt[cell_of(x, y, z, seg)], 1);
}

// Each scan block owns 4096 cells; thread owns 16 contiguous cells.
__global__ void scan1_kernel() {
    __shared__ int red[256];
    const int tid = threadIdx.x;
    const int base = blockIdx.x * 4096 + tid * 16;
    int s = 0;
    if (base < TOTC) {
        const int4* p = reinterpret_cast<const int4*>(g_cnt + base);
#pragma unroll
        for (int j = 0; j < 4; j++) {
            int4 v = p[j];
            s += v.x + v.y + v.z + v.w;
        }
    }
    red[tid] = s;
    __syncthreads();
    for (int o = 128; o >= 1; o >>= 1) {
        if (tid < o) red[tid] += red[tid + o];
        __syncthreads();
    }
    if (tid == 0) g_bsum[blockIdx.x] = red[0];
}

__global__ void scan2_kernel() {    // 1 block, 1024 threads
    __shared__ int s[1024];
    const int tid = threadIdx.x;
    int v = (tid < SCAN_BLOCKS) ? g_bsum[tid] : 0;
    s[tid] = v;
    __syncthreads();
    for (int off = 1; off < 1024; off <<= 1) {
        int add = (tid >= off) ? s[tid - off] : 0;
        __syncthreads();
        s[tid] += add;
        __syncthreads();
    }
    if (tid < SCAN_BLOCKS) g_bsum[tid] = s[tid] - v;    // exclusive
    if (tid == 0) g_start[TOTC] = 2 * BPTS;
}

__global__ void scan3_kernel() {
    __shared__ int s[256];
    const int tid = threadIdx.x;
    const int base = blockIdx.x * 4096 + tid * 16;
    int c[16];
    int tsum = 0;
    if (base < TOTC) {
        const int4* p = reinterpret_cast<const int4*>(g_cnt + base);
#pragma unroll
        for (int j = 0; j < 4; j++) {
            int4 v = p[j];
            c[4 * j + 0] = v.x; c[4 * j + 1] = v.y;
            c[4 * j + 2] = v.z; c[4 * j + 3] = v.w;
        }
#pragma unroll
        for (int j = 0; j < 16; j++) tsum += c[j];
    } else {
#pragma unroll
        for (int j = 0; j < 16; j++) c[j] = 0;
    }
    s[tid] = tsum;
    __syncthreads();
    for (int off = 1; off < 256; off <<= 1) {
        int add = (tid >= off) ? s[tid - off] : 0;
        __syncthreads();
        s[tid] += add;
        __syncthreads();
    }
    int run = g_bsum[blockIdx.x] + s[tid] - tsum;   // global exclusive offset
    if (base < TOTC) {
#pragma unroll
        for (int j = 0; j < 16; j++) {
            g_start[base + j] = run;
            g_cnt[base + j] = run;                  // scatter cursor
            run += c[j];
        }
    }
}

__global__ void scatter_kernel(const float* __restrict__ gts,
                               const float* __restrict__ preds) {
    int t = blockIdx.x * 256 + threadIdx.x;
    int db = t < BPTS ? 0 : 1;
    int pi = t - db * BPTS;
    const float* src = db ? preds : gts;
    float x = src[3 * pi], y = src[3 * pi + 1], z = src[3 * pi + 2];
    int seg = (pi >> 13) * 2 + db;
    int pos = atomicAdd(&g_cnt[cell_of(x, y, z, seg)], 1);
    g_pts[pos] = make_float4(x, y, z, 0.5f * (x * x + y * y + z * z));
}

// ---- query phase ----------------------------------------------------------
// Exact ring search. d' = 0.5|q|^2 + 0.5|p|^2 - q.p = d^2/2.
// After completing Chebyshev rings 0..r, any unexplored point is at distance
// >= r*H + (q's min distance to its own cell walls)  -> safe stop bound.
__global__ void __launch_bounds__(256) query_kernel() {
    const int t = blockIdx.x * 256 + threadIdx.x;      // 0..131071
    const int dir = t >> 16;                            // 0: gts->preds, 1: preds->gts
    const int qi = t & 65535;
    const int b = qi >> 13, i = qi & 8191;
    const int qseg = b * 2 + dir;
    const int tseg = b * 2 + (1 - dir);

    float4 q = g_pts[qseg * PPS + i];
    const float nx = -q.x, ny = -q.y, nz = -q.z, qw = q.w;

    const int cx = min(max((int)((q.x + ORIG) * INV_H), 0), G - 1);
    const int cy = min(max((int)((q.y + ORIG) * INV_H), 0), G - 1);
    const int cz = min(max((int)((q.z + ORIG) * INV_H), 0), G - 1);
    const float fx = (q.x + ORIG) - cx * H;
    const float fy = (q.y + ORIG) - cy * H;
    const float fz = (q.z + ORIG) - cz * H;
    const float fmin = fminf(fminf(fminf(fx, H - fx), fminf(fy, H - fy)),
                             fminf(fz, H - fz));

    const int tbase = tseg * CELLS;
    float best = CUDART_INF_F;

    for (int r = 0; r < G; r++) {
        const int z0 = max(cz - r, 0), z1 = min(cz + r, G - 1);
        const int y0 = max(cy - r, 0), y1 = min(cy + r, G - 1);
        const int x0 = max(cx - r, 0), x1 = min(cx + r, G - 1);
        for (int z = z0; z <= z1; z++) {
            const bool zf = (z == cz - r) || (z == cz + r);
            for (int y = y0; y <= y1; y++) {
                const bool yf = (y == cy - r) || (y == cy + r);
                const int rowb = tbase + (z * G + y) * G;
                if (zf || yf) {
                    // full x-row of the shell: cells contiguous -> ONE range
                    const int s = g_start[rowb + x0];
                    const int e = g_start[rowb + x1 + 1];
                    for (int k = s; k < e; k++) {
                        float4 p = g_pts[k];
                        float d = qw + p.w;
                        d = fmaf(nx, p.x, d);
                        d = fmaf(ny, p.y, d);
                        d = fmaf(nz, p.z, d);
                        best = fminf(best, d);
                    }
                } else {
                    // interior row: only x = cx - r and cx + r are on the shell
#pragma unroll
                    for (int u = 0; u < 2; u++) {
                        const int x = u ? cx + r : cx - r;
                        if ((unsigned)x >= (unsigned)G) continue;
                        const int s = g_start[rowb + x];
                        const int e = g_start[rowb + x + 1];
                        for (int k = s; k < e; k++) {
                            float4 p = g_pts[k];
                            float d = qw + p.w;
                            d = fmaf(nx, p.x, d);
                            d = fmaf(ny, p.y, d);
                            d = fmaf(nz, p.z, d);
                            best = fminf(best, d);
                        }
                    }
                }
            }
        }
        const float bnd = r * H + fmin;
        if (2.0f * best <= bnd * bnd) break;
    }

    // clamp (reference max(d2,0) commutes with min), block-sum in fixed tree
    __shared__ float sred[256];
    sred[threadIdx.x] = fmaxf(best, 0.0f);
    __syncthreads();
    for (int o = 128; o >= 1; o >>= 1) {
        if (threadIdx.x < o) sred[threadIdx.x] += sred[threadIdx.x + o];
        __syncthreads();
    }
    if (threadIdx.x == 0) g_part[blockIdx.x] = sred[0];
}

__global__ void final_kernel(float* __restrict__ out) {
    __shared__ float sred[256];
    const int tid = threadIdx.x;
    sred[tid] = g_part[tid] + g_part[tid + 256];
    __syncthreads();
    for (int o = 128; o >= 1; o >>= 1) {
        if (tid < o) sred[tid] += sred[tid + o];
        __syncthreads();
    }
    // d^2 = 2*d'; each direction is a mean over 65536 points.
    if (tid == 0) out[0] = sred[0] * (2.0f / 65536.0f);
}

extern "C" void kernel_launch(void* const* d_in, const int* in_sizes, int n_in,
                              void* d_out, int out_size) {
    const float* gts   = (const float*)d_in[0];
    const float* preds = (const float*)d_in[1];
    float* out = (float*)d_out;

    zero_kernel<<<(TOTC + 255) / 256, 256>>>();
    count_kernel<<<512, 256>>>(gts, preds);
    scan1_kernel<<<SCAN_BLOCKS, 256>>>();
    scan2_kernel<<<1, 1024>>>();
    scan3_kernel<<<SCAN_BLOCKS, 256>>>();
    scatter_kernel<<<512, 256>>>(gts, preds);
    query_kernel<<<512, 256>>>();
    final_kernel<<<1, 256>>>(out);
}

// round 5
// speedup vs baseline: 2.4296x; 2.4296x over previous
#include <cuda_runtime.h>
#include <math_constants.h>

// Problem shape (fixed): B=8, N=M=8192, D=3, fp32, scalar output.
// Exact grid-accelerated NN with capped ring search + brute-force overflow.
#define BB 8
#define PPS 8192                 // points per (batch, side)
#define BPTS (BB * PPS)          // 65536 points per side
#define NQ (2 * BPTS)            // 131072 queries (both directions)
#define G 52                     // grid cells per axis
#define CELLS (G * G * G)        // 140608
#define NSEG (BB * 2)            // 16 (batch, side) segments
#define TOTC (NSEG * CELLS)      // 2249728 cells total
#define H 0.25f
#define INV_H 4.0f
#define ORIG 6.5f                // grid covers [-6.5,6.5); inputs bounded ~|5.2|
#define SCAN_BLOCKS 576          // 576 * 4096 >= TOTC
#define R_CAP 3                  // max Chebyshev ring before overflow

// Static scratch (no allocations allowed).
__device__ int    g_cnt[TOTC];       // cell counts, then scatter cursors
__device__ int    g_start[TOTC + 1]; // global exclusive scan of counts
__device__ int    g_bsum[1024];      // per-scan-block sums
__device__ float4 g_pts[NQ];         // cell-sorted points (x,y,z, 0.5*|p|^2)
__device__ float  g_best[NQ];        // per-query clamped min d' = d^2/2
__device__ int    g_ovf[NQ];         // overflow query ids
__device__ int    g_ovfcnt;          // overflow count

__device__ __forceinline__ int cell_of(float x, float y, float z, int seg) {
    int cx = min(max((int)((x + ORIG) * INV_H), 0), G - 1);
    int cy = min(max((int)((y + ORIG) * INV_H), 0), G - 1);
    int cz = min(max((int)((z + ORIG) * INV_H), 0), G - 1);
    return seg * CELLS + (cz * G + cy) * G + cx;
}

// ---- build phase ----------------------------------------------------------
__global__ void zero_kernel() {
    int i = blockIdx.x * 256 + threadIdx.x;
    if (i < TOTC) g_cnt[i] = 0;
    if (i == 0) g_ovfcnt = 0;
}

__global__ void count_kernel(const float* __restrict__ gts,
                             const float* __restrict__ preds) {
    int t = blockIdx.x * 256 + threadIdx.x;            // 0..131071
    int db = t < BPTS ? 0 : 1;
    int pi = t - db * BPTS;
    const float* src = db ? preds : gts;
    float x = src[3 * pi], y = src[3 * pi + 1], z = src[3 * pi + 2];
    int seg = (pi >> 13) * 2 + db;
    atomicAdd(&g_cnt[cell_of(x, y, z, seg)], 1);
}

// Each scan block owns 4096 cells; thread owns 16 contiguous cells.
__global__ void scan1_kernel() {
    __shared__ int red[256];
    const int tid = threadIdx.x;
    const int base = blockIdx.x * 4096 + tid * 16;
    int s = 0;
    if (base < TOTC) {
        const int4* p = reinterpret_cast<const int4*>(g_cnt + base);
#pragma unroll
        for (int j = 0; j < 4; j++) {
            int4 v = p[j];
            s += v.x + v.y + v.z + v.w;
        }
    }
    red[tid] = s;
    __syncthreads();
    for (int o = 128; o >= 1; o >>= 1) {
        if (tid < o) red[tid] += red[tid + o];
        __syncthreads();
    }
    if (tid == 0) g_bsum[blockIdx.x] = red[0];
}

__global__ void scan2_kernel() {    // 1 block, 1024 threads
    __shared__ int s[1024];
    const int tid = threadIdx.x;
    int v = (tid < SCAN_BLOCKS) ? g_bsum[tid] : 0;
    s[tid] = v;
    __syncthreads();
    for (int off = 1; off < 1024; off <<= 1) {
        int add = (tid >= off) ? s[tid - off] : 0;
        __syncthreads();
        s[tid] += add;
        __syncthreads();
    }
    if (tid < SCAN_BLOCKS) g_bsum[tid] = s[tid] - v;    // exclusive
    if (tid == 0) g_start[TOTC] = NQ;
}

__global__ void scan3_kernel() {
    __shared__ int s[256];
    const int tid = threadIdx.x;
    const int base = blockIdx.x * 4096 + tid * 16;
    int c[16];
    int tsum = 0;
    if (base < TOTC) {
        const int4* p = reinterpret_cast<const int4*>(g_cnt + base);
#pragma unroll
        for (int j = 0; j < 4; j++) {
            int4 v = p[j];
            c[4 * j + 0] = v.x; c[4 * j + 1] = v.y;
            c[4 * j + 2] = v.z; c[4 * j + 3] = v.w;
        }
#pragma unroll
        for (int j = 0; j < 16; j++) tsum += c[j];
    } else {
#pragma unroll
        for (int j = 0; j < 16; j++) c[j] = 0;
    }
    s[tid] = tsum;
    __syncthreads();
    for (int off = 1; off < 256; off <<= 1) {
        int add = (tid >= off) ? s[tid - off] : 0;
        __syncthreads();
        s[tid] += add;
        __syncthreads();
    }
    int run = g_bsum[blockIdx.x] + s[tid] - tsum;   // global exclusive offset
    if (base < TOTC) {
#pragma unroll
        for (int j = 0; j < 16; j++) {
            g_start[base + j] = run;
            g_cnt[base + j] = run;                  // scatter cursor
            run += c[j];
        }
    }
}

__global__ void scatter_kernel(const float* __restrict__ gts,
                               const float* __restrict__ preds) {
    int t = blockIdx.x * 256 + threadIdx.x;
    int db = t < BPTS ? 0 : 1;
    int pi = t - db * BPTS;
    const float* src = db ? preds : gts;
    float x = src[3 * pi], y = src[3 * pi + 1], z = src[3 * pi + 2];
    int seg = (pi >> 13) * 2 + db;
    int pos = atomicAdd(&g_cnt[cell_of(x, y, z, seg)], 1);
    g_pts[pos] = make_float4(x, y, z, 0.5f * (x * x + y * y + z * z));
}

// ---- query phase ----------------------------------------------------------
// Exact capped ring search. d' = 0.5|q|^2 + 0.5|p|^2 - q.p = d^2/2.
// After completing rings 0..r, unexplored points are at distance >= r*H + fmin
// (fmin = query's min distance to its own cell walls). If not converged by
// ring R_CAP, the query goes to the brute-force overflow kernel.
__global__ void __launch_bounds__(256) query_kernel() {
    const int t = blockIdx.x * 256 + threadIdx.x;      // 0..131071
    const int dir = t >> 16;                            // 0: gts side, 1: preds side
    const int qi = t & 65535;
    const int b = qi >> 13, i = qi & 8191;
    const int qseg = b * 2 + dir;
    const int tseg = b * 2 + (1 - dir);

    float4 q = g_pts[qseg * PPS + i];   // sorted order -> lanes share cells
    const float nx = -q.x, ny = -q.y, nz = -q.z, qw = q.w;

    const int cx = min(max((int)((q.x + ORIG) * INV_H), 0), G - 1);
    const int cy = min(max((int)((q.y + ORIG) * INV_H), 0), G - 1);
    const int cz = min(max((int)((q.z + ORIG) * INV_H), 0), G - 1);
    const float fx = (q.x + ORIG) - cx * H;
    const float fy = (q.y + ORIG) - cy * H;
    const float fz = (q.z + ORIG) - cz * H;
    const float fmin = fminf(fminf(fminf(fx, H - fx), fminf(fy, H - fy)),
                             fminf(fz, H - fz));

    const int tbase = tseg * CELLS;
    float best = CUDART_INF_F;
    bool done = false;

    for (int r = 0; r <= R_CAP; r++) {
        const int z0 = max(cz - r, 0), z1 = min(cz + r, G - 1);
        const int y0 = max(cy - r, 0), y1 = min(cy + r, G - 1);
        const int x0 = max(cx - r, 0), x1 = min(cx + r, G - 1);
        for (int z = z0; z <= z1; z++) {
            const bool zf = (z == cz - r) || (z == cz + r);
            for (int y = y0; y <= y1; y++) {
                const bool yf = (y == cy - r) || (y == cy + r);
                const int rowb = tbase + (z * G + y) * G;
                if (zf || yf) {
                    // full x-row of the shell: one contiguous range
                    const int s = g_start[rowb + x0];
                    const int e = g_start[rowb + x1 + 1];
                    for (int k = s; k < e; k++) {
                        float4 p = g_pts[k];
                        float d = qw + p.w;
                        d = fmaf(nx, p.x, d);
                        d = fmaf(ny, p.y, d);
                        d = fmaf(nz, p.z, d);
                        best = fminf(best, d);
                    }
                } else {
                    // interior row: only x = cx-r and cx+r are on the shell
#pragma unroll
                    for (int u = 0; u < 2; u++) {
                        const int x = u ? cx + r : cx - r;
                        if ((unsigned)x >= (unsigned)G) continue;
                        const int s = g_start[rowb + x];
                        const int e = g_start[rowb + x + 1];
                        for (int k = s; k < e; k++) {
                            float4 p = g_pts[k];
                            float d = qw + p.w;
                            d = fmaf(nx, p.x, d);
                            d = fmaf(ny, p.y, d);
                            d = fmaf(nz, p.z, d);
                            best = fminf(best, d);
                        }
                    }
                }
            }
        }
        const float bnd = r * H + fmin;
        if (2.0f * best <= bnd * bnd) { done = true; break; }
    }

    if (done) {
        g_best[t] = fmaxf(best, 0.0f);
    } else {
        int pos = atomicAdd(&g_ovfcnt, 1);   // rare (~0.2-1% of queries)
        g_ovf[pos] = t;
    }
}

// Warp-per-query brute force over the full opposing segment (8192 points).
// Coalesced float4 loads, lanes strided; shfl-min reduce (order-independent).
__global__ void __launch_bounds__(256) brute_kernel() {
    const int cnt = g_ovfcnt;
    const int lane = threadIdx.x & 31;
    const int warp = (blockIdx.x * 256 + threadIdx.x) >> 5;   // 0..2047
    for (int j = warp; j < cnt; j += 2048) {
        const int t = g_ovf[j];
        const int dir = t >> 16;
        const int qi = t & 65535;
        const int b = qi >> 13, i = qi & 8191;
        const int qseg = b * 2 + dir;
        const int tseg = b * 2 + (1 - dir);

        float4 q = g_pts[qseg * PPS + i];
        const float nx = -q.x, ny = -q.y, nz = -q.z, qw = q.w;
        const float4* tp = g_pts + tseg * PPS;

        float best = CUDART_INF_F;
        for (int k = lane; k < PPS; k += 32) {
            float4 p = tp[k];
            float d = qw + p.w;
            d = fmaf(nx, p.x, d);
            d = fmaf(ny, p.y, d);
            d = fmaf(nz, p.z, d);
            best = fminf(best, d);
        }
#pragma unroll
        for (int o = 16; o >= 1; o >>= 1)
            best = fminf(best, __shfl_xor_sync(0xFFFFFFFFu, best, o));
        if (lane == 0) g_best[t] = fmaxf(best, 0.0f);
    }
}

// Single-block deterministic sum of all 131072 per-query results.
__global__ void final_kernel(float* __restrict__ out) {
    __shared__ float sred[1024];
    const int tid = threadIdx.x;
    float acc = 0.0f;
    const float4* p = reinterpret_cast<const float4*>(g_best);
#pragma unroll 8
    for (int i = tid; i < NQ / 4; i += 1024) {
        float4 v = p[i];
        acc += (v.x + v.y) + (v.z + v.w);
    }
    sred[tid] = acc;
    __syncthreads();
    for (int o = 512; o >= 1; o >>= 1) {
        if (tid < o) sred[tid] += sred[tid + o];
        __syncthreads();
    }
    // d^2 = 2*d'; each direction is a mean over 65536 points.
    if (tid == 0) out[0] = sred[0] * (2.0f / 65536.0f);
}

extern "C" void kernel_launch(void* const* d_in, const int* in_sizes, int n_in,
                              void* d_out, int out_size) {
    const float* gts   = (const float*)d_in[0];
    const float* preds = (const float*)d_in[1];
    float* out = (float*)d_out;

    zero_kernel<<<(TOTC + 255) / 256, 256>>>();
    count_kernel<<<512, 256>>>(gts, preds);
    scan1_kernel<<<SCAN_BLOCKS, 256>>>();
    scan2_kernel<<<1, 1024>>>();
    scan3_kernel<<<SCAN_BLOCKS, 256>>>();
    scatter_kernel<<<512, 256>>>(gts, preds);
    query_kernel<<<512, 256>>>();
    brute_kernel<<<256, 256>>>();
    final_kernel<<<1, 1024>>>(out);
}

// round 6
// speedup vs baseline: 2.7583x; 1.1353x over previous
#include <cuda_runtime.h>
#include <math_constants.h>

// Problem shape (fixed): B=8, N=M=8192, D=3, fp32, scalar output.
// Exact grid-accelerated NN with capped ring search + brute-force overflow.
#define BB 8
#define PPS 8192                 // points per (batch, side)
#define BPTS (BB * PPS)          // 65536 points per side
#define NQ (2 * BPTS)            // 131072 queries (both directions)
#define G 48                     // grid cells per axis
#define CELLS (G * G * G)        // 110592
#define NSEG (BB * 2)            // 16 (batch, side) segments
#define TOTC (NSEG * CELLS)      // 1769472 cells total
#define H 0.25f
#define INV_H 4.0f
#define ORIG 6.0f                // grid covers [-6,6); |coords| < ~5.4 w.h.p.
#define SCAN_BLOCKS 432          // 432 * 4096 == TOTC
#define R_CAP 3                  // max Chebyshev ring before overflow

// Static scratch (no allocations allowed). All zero at module load;
// g_cnt/g_ovfcnt are re-zeroed each call by query/final (see below).
__device__ int    g_cnt[TOTC];       // cell counts, then scatter cursors
__device__ int    g_start[TOTC + 1]; // global exclusive scan of counts
__device__ int    g_bsum[1024];      // per-scan-block sums
__device__ float4 g_pts[NQ];         // cell-sorted points (x,y,z, 0.5*|p|^2)
__device__ float  g_best[NQ];        // per-query clamped min d' = d^2/2
__device__ int    g_ovf[NQ];         // overflow query ids
__device__ int    g_ovfcnt;          // overflow count

__device__ __forceinline__ int cell_of(float x, float y, float z, int seg) {
    int cx = min(max((int)((x + ORIG) * INV_H), 0), G - 1);
    int cy = min(max((int)((y + ORIG) * INV_H), 0), G - 1);
    int cz = min(max((int)((z + ORIG) * INV_H), 0), G - 1);
    return seg * CELLS + (cz * G + cy) * G + cx;
}

// ---- build phase ----------------------------------------------------------
// (g_cnt is guaranteed zero here: module-load .bss on first call, re-zeroed
//  by query_kernel on every call thereafter.)
__global__ void count_kernel(const float* __restrict__ gts,
                             const float* __restrict__ preds) {
    int t = blockIdx.x * 256 + threadIdx.x;            // 0..131071
    int db = t < BPTS ? 0 : 1;
    int pi = t - db * BPTS;
    const float* src = db ? preds : gts;
    float x = src[3 * pi], y = src[3 * pi + 1], z = src[3 * pi + 2];
    int seg = (pi >> 13) * 2 + db;
    atomicAdd(&g_cnt[cell_of(x, y, z, seg)], 1);
}

// Each scan block owns 4096 cells; thread owns 16 contiguous cells.
__global__ void scan1_kernel() {
    __shared__ int red[256];
    const int tid = threadIdx.x;
    const int base = blockIdx.x * 4096 + tid * 16;
    const int4* p = reinterpret_cast<const int4*>(g_cnt + base);
    int s = 0;
#pragma unroll
    for (int j = 0; j < 4; j++) {
        int4 v = p[j];
        s += v.x + v.y + v.z + v.w;
    }
    red[tid] = s;
    __syncthreads();
    for (int o = 128; o >= 1; o >>= 1) {
        if (tid < o) red[tid] += red[tid + o];
        __syncthreads();
    }
    if (tid == 0) g_bsum[blockIdx.x] = red[0];
}

__global__ void scan2_kernel() {    // 1 block, 512 threads; scans 432 sums
    __shared__ int s[512];
    const int tid = threadIdx.x;
    int v = (tid < SCAN_BLOCKS) ? g_bsum[tid] : 0;
    s[tid] = v;
    __syncthreads();
    for (int off = 1; off < 512; off <<= 1) {
        int add = (tid >= off) ? s[tid - off] : 0;
        __syncthreads();
        s[tid] += add;
        __syncthreads();
    }
    if (tid < SCAN_BLOCKS) g_bsum[tid] = s[tid] - v;    // exclusive
    if (tid == 0) g_start[TOTC] = NQ;
}

__global__ void scan3_kernel() {
    __shared__ int s[256];
    const int tid = threadIdx.x;
    const int base = blockIdx.x * 4096 + tid * 16;
    int c[16];
    const int4* p = reinterpret_cast<const int4*>(g_cnt + base);
#pragma unroll
    for (int j = 0; j < 4; j++) {
        int4 v = p[j];
        c[4 * j + 0] = v.x; c[4 * j + 1] = v.y;
        c[4 * j + 2] = v.z; c[4 * j + 3] = v.w;
    }
    int tsum = 0;
#pragma unroll
    for (int j = 0; j < 16; j++) tsum += c[j];
    s[tid] = tsum;
    __syncthreads();
    for (int off = 1; off < 256; off <<= 1) {
        int add = (tid >= off) ? s[tid - off] : 0;
        __syncthreads();
        s[tid] += add;
        __syncthreads();
    }
    int run = g_bsum[blockIdx.x] + s[tid] - tsum;   // global exclusive offset
#pragma unroll
    for (int j = 0; j < 16; j++) {
        g_start[base + j] = run;
        g_cnt[base + j] = run;                      // scatter cursor
        run += c[j];
    }
}

__global__ void scatter_kernel(const float* __restrict__ gts,
                               const float* __restrict__ preds) {
    int t = blockIdx.x * 256 + threadIdx.x;
    int db = t < BPTS ? 0 : 1;
    int pi = t - db * BPTS;
    const float* src = db ? preds : gts;
    float x = src[3 * pi], y = src[3 * pi + 1], z = src[3 * pi + 2];
    int seg = (pi >> 13) * 2 + db;
    int pos = atomicAdd(&g_cnt[cell_of(x, y, z, seg)], 1);
    g_pts[pos] = make_float4(x, y, z, 0.5f * (x * x + y * y + z * z));
}

// ---- query phase ----------------------------------------------------------
// Candidate scan with two fmin accumulators (halves the FMNMX dep chain,
// doubles load-level parallelism).
__device__ __forceinline__ void scan_range(int s, int e,
                                           float nx, float ny, float nz, float qw,
                                           float& b0, float& b1) {
    int k = s;
    for (; k + 1 < e; k += 2) {
        float4 p = g_pts[k];
        float4 p2 = g_pts[k + 1];
        float d = qw + p.w;
        d = fmaf(nx, p.x, d);
        d = fmaf(ny, p.y, d);
        d = fmaf(nz, p.z, d);
        float d2 = qw + p2.w;
        d2 = fmaf(nx, p2.x, d2);
        d2 = fmaf(ny, p2.y, d2);
        d2 = fmaf(nz, p2.z, d2);
        b0 = fminf(b0, d);
        b1 = fminf(b1, d2);
    }
    if (k < e) {
        float4 p = g_pts[k];
        float d = qw + p.w;
        d = fmaf(nx, p.x, d);
        d = fmaf(ny, p.y, d);
        d = fmaf(nz, p.z, d);
        b0 = fminf(b0, d);
    }
}

// Exact capped ring search. d' = 0.5|q|^2 + 0.5|p|^2 - q.p = d^2/2.
// After completing rings 0..r, unexplored points are at distance >= r*H + fmin
// (fmin = query's min distance to its own cell walls). Non-converged queries
// go to the brute-force overflow kernel. Also re-zeros g_cnt for next call.
__global__ void __launch_bounds__(256) query_kernel() {
    const int t = blockIdx.x * 256 + threadIdx.x;      // 0..131071
    // Re-zero cell counters for the next kernel_launch (g_cnt dead after scatter).
    {
        int4* cz4 = reinterpret_cast<int4*>(g_cnt);
        const int4 z4 = make_int4(0, 0, 0, 0);
        for (int i = t; i < TOTC / 4; i += NQ) cz4[i] = z4;
    }

    const int dir = t >> 16;                            // 0: gts side, 1: preds side
    const int qi = t & 65535;
    const int b = qi >> 13, i = qi & 8191;
    const int qseg = b * 2 + dir;
    const int tseg = b * 2 + (1 - dir);

    float4 q = g_pts[qseg * PPS + i];   // sorted order -> lanes share cells
    const float nx = -q.x, ny = -q.y, nz = -q.z, qw = q.w;

    const int cx = min(max((int)((q.x + ORIG) * INV_H), 0), G - 1);
    const int cy = min(max((int)((q.y + ORIG) * INV_H), 0), G - 1);
    const int cz = min(max((int)((q.z + ORIG) * INV_H), 0), G - 1);
    const float fx = (q.x + ORIG) - cx * H;
    const float fy = (q.y + ORIG) - cy * H;
    const float fz = (q.z + ORIG) - cz * H;
    const float fmin = fminf(fminf(fminf(fx, H - fx), fminf(fy, H - fy)),
                             fminf(fz, H - fz));

    const int tbase = tseg * CELLS;
    float b0 = CUDART_INF_F, b1 = CUDART_INF_F;
    bool done = false;

    for (int r = 0; r <= R_CAP; r++) {
        const int z0 = max(cz - r, 0), z1 = min(cz + r, G - 1);
        const int y0 = max(cy - r, 0), y1 = min(cy + r, G - 1);
        const int x0 = max(cx - r, 0), x1 = min(cx + r, G - 1);
        for (int z = z0; z <= z1; z++) {
            const bool zf = (z == cz - r) || (z == cz + r);
            for (int y = y0; y <= y1; y++) {
                const bool yf = (y == cy - r) || (y == cy + r);
                const int rowb = tbase + (z * G + y) * G;
                if (zf || yf) {
                    // full x-row of the shell: one contiguous range
                    scan_range(g_start[rowb + x0], g_start[rowb + x1 + 1],
                               nx, ny, nz, qw, b0, b1);
                } else {
                    // interior row: only x = cx-r and cx+r are on the shell
#pragma unroll
                    for (int u = 0; u < 2; u++) {
                        const int x = u ? cx + r : cx - r;
                        if ((unsigned)x >= (unsigned)G) continue;
                        scan_range(g_start[rowb + x], g_start[rowb + x + 1],
                                   nx, ny, nz, qw, b0, b1);
                    }
                }
            }
        }
        const float bnd = r * H + fmin;
        if (2.0f * fminf(b0, b1) <= bnd * bnd) { done = true; break; }
    }

    if (done) {
        g_best[t] = fmaxf(fminf(b0, b1), 0.0f);
    } else {
        int pos = atomicAdd(&g_ovfcnt, 1);   // rare tail queries
        g_ovf[pos] = t;
    }
}

// Warp-per-query brute force over the full opposing segment (8192 points).
// Coalesced float4 loads, lanes strided; shfl-min reduce (order-independent).
__global__ void __launch_bounds__(256) brute_kernel() {
    const int cnt = g_ovfcnt;
    const int lane = threadIdx.x & 31;
    const int warp = (blockIdx.x * 256 + threadIdx.x) >> 5;   // 0..2047
    for (int j = warp; j < cnt; j += 2048) {
        const int t = g_ovf[j];
        const int dir = t >> 16;
        const int qi = t & 65535;
        const int b = qi >> 13, i = qi & 8191;
        const int qseg = b * 2 + dir;
        const int tseg = b * 2 + (1 - dir);

        float4 q = g_pts[qseg * PPS + i];
        const float nx = -q.x, ny = -q.y, nz = -q.z, qw = q.w;
        const float4* tp = g_pts + tseg * PPS;

        float best = CUDART_INF_F;
        for (int k = lane; k < PPS; k += 32) {
            float4 p = tp[k];
            float d = qw + p.w;
            d = fmaf(nx, p.x, d);
            d = fmaf(ny, p.y, d);
            d = fmaf(nz, p.z, d);
            best = fminf(best, d);
        }
#pragma unroll
        for (int o = 16; o >= 1; o >>= 1)
            best = fminf(best, __shfl_xor_sync(0xFFFFFFFFu, best, o));
        if (lane == 0) g_best[t] = fmaxf(best, 0.0f);
    }
}

// Single-block deterministic sum of all 131072 per-query results.
// Also resets g_ovfcnt for the next kernel_launch (brute already consumed it).
__global__ void final_kernel(float* __restrict__ out) {
    __shared__ float sred[1024];
    const int tid = threadIdx.x;
    float acc = 0.0f;
    const float4* p = reinterpret_cast<const float4*>(g_best);
#pragma unroll 8
    for (int i = tid; i < NQ / 4; i += 1024) {
        float4 v = p[i];
        acc += (v.x + v.y) + (v.z + v.w);
    }
    sred[tid] = acc;
    __syncthreads();
    for (int o = 512; o >= 1; o >>= 1) {
        if (tid < o) sred[tid] += sred[tid + o];
        __syncthreads();
    }
    if (tid == 0) {
        // d^2 = 2*d'; each direction is a mean over 65536 points.
        out[0] = sred[0] * (2.0f / 65536.0f);
        g_ovfcnt = 0;
    }
}

extern "C" void kernel_launch(void* const* d_in, const int* in_sizes, int n_in,
                              void* d_out, int out_size) {
    const float* gts   = (const float*)d_in[0];
    const float* preds = (const float*)d_in[1];
    float* out = (float*)d_out;

    count_kernel<<<512, 256>>>(gts, preds);
    scan1_kernel<<<SCAN_BLOCKS, 256>>>();
    scan2_kernel<<<1, 512>>>();
    scan3_kernel<<<SCAN_BLOCKS, 256>>>();
    scatter_kernel<<<512, 256>>>(gts, preds);
    query_kernel<<<512, 256>>>();
    brute_kernel<<<256, 256>>>();
    final_kernel<<<1, 1024>>>(out);
}

// round 7
// speedup vs baseline: 2.9899x; 1.0840x over previous
#include <cuda_runtime.h>
#include <math_constants.h>

// Problem shape (fixed): B=8, N=M=8192, D=3, fp32, scalar output.
// Exact grid-accelerated NN with capped ring search + brute-force overflow.
#define BB 8
#define PPS 8192                 // points per (batch, side)
#define BPTS (BB * PPS)          // 65536 points per side
#define NQ (2 * BPTS)            // 131072 queries (both directions)
#define G 32                     // grid cells per axis (power of 2)
#define CELLS (G * G * G)        // 32768
#define NSEG (BB * 2)            // 16 (batch, side) segments
#define TOTC (NSEG * CELLS)      // 524288 cells total
#define H 0.25f
#define INV_H 4.0f
#define ORIG 4.0f                // grid covers [-4,4); outside clamps (exact-safe)
#define SCAN_BLOCKS 128          // 128 * 4096 == TOTC
#define R_CAP 3                  // max Chebyshev ring before overflow

// Static scratch (no allocations allowed). Zero at module load;
// g_cnt / g_ovfcnt are re-zeroed each call by query/final.
__device__ int    g_cnt[TOTC];       // cell counts, then scatter cursors
__device__ int    g_start[TOTC + 1]; // global exclusive scan of counts
__device__ int    g_bsum[SCAN_BLOCKS]; // per-scan-block sums
__device__ float4 g_pts[NQ];         // cell-sorted points (x,y,z, 0.5*|p|^2)
__device__ float  g_best[NQ];        // per-query clamped min d' = d^2/2
__device__ int    g_ovf[NQ];         // overflow query ids
__device__ int    g_ovfcnt;          // overflow count

__device__ __forceinline__ int cell_of(float x, float y, float z, int seg) {
    int cx = min(max((int)((x + ORIG) * INV_H), 0), G - 1);
    int cy = min(max((int)((y + ORIG) * INV_H), 0), G - 1);
    int cz = min(max((int)((z + ORIG) * INV_H), 0), G - 1);
    return (seg << 15) | (cz << 10) | (cy << 5) | cx;
}

// ---- build phase ----------------------------------------------------------
__global__ void count_kernel(const float* __restrict__ gts,
                             const float* __restrict__ preds) {
    int t = blockIdx.x * 256 + threadIdx.x;            // 0..131071
    int db = t < BPTS ? 0 : 1;
    int pi = t - db * BPTS;
    const float* src = db ? preds : gts;
    float x = src[3 * pi], y = src[3 * pi + 1], z = src[3 * pi + 2];
    int seg = (pi >> 13) * 2 + db;
    atomicAdd(&g_cnt[cell_of(x, y, z, seg)], 1);
}

// Each scan block owns 4096 cells; thread owns 16 contiguous cells.
__global__ void scan1_kernel() {
    __shared__ int red[256];
    const int tid = threadIdx.x;
    const int base = blockIdx.x * 4096 + tid * 16;
    const int4* p = reinterpret_cast<const int4*>(g_cnt + base);
    int s = 0;
#pragma unroll
    for (int j = 0; j < 4; j++) {
        int4 v = p[j];
        s += v.x + v.y + v.z + v.w;
    }
    red[tid] = s;
    __syncthreads();
    for (int o = 128; o >= 1; o >>= 1) {
        if (tid < o) red[tid] += red[tid + o];
        __syncthreads();
    }
    if (tid == 0) g_bsum[blockIdx.x] = red[0];
}

// Fused inter-block prefix (redundant per block: 128 values) + intra scan +
// write of g_start and scatter cursors.
__global__ void scan3_kernel() {
    __shared__ int s[256];
    __shared__ int basesum;
    const int tid = threadIdx.x;
    const int bid = blockIdx.x;

    // --- fused scan2: sum of g_bsum[j] for j < bid ---
    s[tid] = (tid < SCAN_BLOCKS && tid < bid) ? g_bsum[tid] : 0;
    __syncthreads();
    for (int o = 128; o >= 1; o >>= 1) {
        if (tid < o) s[tid] += s[tid + o];
        __syncthreads();
    }
    if (tid == 0) basesum = s[0];
    __syncthreads();
    const int blkbase = basesum;
    __syncthreads();                         // s[] reused below

    // --- intra-block scan over 4096 cells ---
    const int base = bid * 4096 + tid * 16;
    int c[16];
    const int4* p = reinterpret_cast<const int4*>(g_cnt + base);
#pragma unroll
    for (int j = 0; j < 4; j++) {
        int4 v = p[j];
        c[4 * j + 0] = v.x; c[4 * j + 1] = v.y;
        c[4 * j + 2] = v.z; c[4 * j + 3] = v.w;
    }
    int tsum = 0;
#pragma unroll
    for (int j = 0; j < 16; j++) tsum += c[j];
    s[tid] = tsum;
    __syncthreads();
    for (int off = 1; off < 256; off <<= 1) {
        int add = (tid >= off) ? s[tid - off] : 0;
        __syncthreads();
        s[tid] += add;
        __syncthreads();
    }
    int run = blkbase + s[tid] - tsum;       // global exclusive offset
#pragma unroll
    for (int j = 0; j < 16; j++) {
        g_start[base + j] = run;
        g_cnt[base + j] = run;               // scatter cursor
        run += c[j];
    }
    if (bid == 0 && tid == 0) g_start[TOTC] = NQ;
}

__global__ void scatter_kernel(const float* __restrict__ gts,
                               const float* __restrict__ preds) {
    int t = blockIdx.x * 256 + threadIdx.x;
    int db = t < BPTS ? 0 : 1;
    int pi = t - db * BPTS;
    const float* src = db ? preds : gts;
    float x = src[3 * pi], y = src[3 * pi + 1], z = src[3 * pi + 2];
    int seg = (pi >> 13) * 2 + db;
    int pos = atomicAdd(&g_cnt[cell_of(x, y, z, seg)], 1);
    g_pts[pos] = make_float4(x, y, z, 0.5f * (x * x + y * y + z * z));
}

// ---- query phase ----------------------------------------------------------
// Candidate scan with two fmin accumulators (short dep chains, 2x load MLP).
__device__ __forceinline__ void scan_range(int s, int e,
                                           float nx, float ny, float nz, float qw,
                                           float& b0, float& b1) {
    int k = s;
    for (; k + 1 < e; k += 2) {
        float4 p = g_pts[k];
        float4 p2 = g_pts[k + 1];
        float d = qw + p.w;
        d = fmaf(nx, p.x, d);
        d = fmaf(ny, p.y, d);
        d = fmaf(nz, p.z, d);
        float d2 = qw + p2.w;
        d2 = fmaf(nx, p2.x, d2);
        d2 = fmaf(ny, p2.y, d2);
        d2 = fmaf(nz, p2.z, d2);
        b0 = fminf(b0, d);
        b1 = fminf(b1, d2);
    }
    if (k < e) {
        float4 p = g_pts[k];
        float d = qw + p.w;
        d = fmaf(nx, p.x, d);
        d = fmaf(ny, p.y, d);
        d = fmaf(nz, p.z, d);
        b0 = fminf(b0, d);
    }
}

// Exact capped ring search. d' = 0.5|q|^2 + 0.5|p|^2 - q.p = d^2/2.
// After completing rings 0..r, unexplored points are >= r*H + fmin away
// (fmin = query's min distance to its own cell walls; clamped queries get a
// smaller/negative fmin -> conservative -> safe). Non-converged queries go to
// the brute-force overflow kernel. Also re-zeros g_cnt for the next call.
__global__ void __launch_bounds__(256) query_kernel() {
    const int t = blockIdx.x * 256 + threadIdx.x;      // 0..131071
    // Re-zero cell counters for the next kernel_launch (exactly 1 int4 each).
    reinterpret_cast<int4*>(g_cnt)[t] = make_int4(0, 0, 0, 0);

    const int dir = t >> 16;                            // 0: gts side, 1: preds side
    const int qi = t & 65535;
    const int b = qi >> 13, i = qi & 8191;
    const int qseg = b * 2 + dir;
    const int tseg = b * 2 + (1 - dir);

    float4 q = g_pts[qseg * PPS + i];   // sorted order -> lanes share cells
    const float nx = -q.x, ny = -q.y, nz = -q.z, qw = q.w;

    const int cx = min(max((int)((q.x + ORIG) * INV_H), 0), G - 1);
    const int cy = min(max((int)((q.y + ORIG) * INV_H), 0), G - 1);
    const int cz = min(max((int)((q.z + ORIG) * INV_H), 0), G - 1);
    const float fx = (q.x + ORIG) - cx * H;
    const float fy = (q.y + ORIG) - cy * H;
    const float fz = (q.z + ORIG) - cz * H;
    const float fmin = fminf(fminf(fminf(fx, H - fx), fminf(fy, H - fy)),
                             fminf(fz, H - fz));

    const int tbase = tseg << 15;
    float b0 = CUDART_INF_F, b1 = CUDART_INF_F;
    bool done = false;

    for (int r = 0; r <= R_CAP; r++) {
        const int z0 = max(cz - r, 0), z1 = min(cz + r, G - 1);
        const int y0 = max(cy - r, 0), y1 = min(cy + r, G - 1);
        const int x0 = max(cx - r, 0), x1 = min(cx + r, G - 1);
        for (int z = z0; z <= z1; z++) {
            const bool zf = (z == cz - r) || (z == cz + r);
            for (int y = y0; y <= y1; y++) {
                const bool yf = (y == cy - r) || (y == cy + r);
                const int rowb = tbase | (z << 10) | (y << 5);
                if (zf || yf) {
                    // full x-row of the shell: one contiguous range
                    scan_range(g_start[rowb + x0], g_start[rowb + x1 + 1],
                               nx, ny, nz, qw, b0, b1);
                } else {
                    // interior row: only x = cx-r and cx+r are on the shell
#pragma unroll
                    for (int u = 0; u < 2; u++) {
                        const int x = u ? cx + r : cx - r;
                        if ((unsigned)x >= (unsigned)G) continue;
                        scan_range(g_start[rowb + x], g_start[rowb + x + 1],
                                   nx, ny, nz, qw, b0, b1);
                    }
                }
            }
        }
        const float bnd = r * H + fmin;
        if (2.0f * fminf(b0, b1) <= bnd * bnd) { done = true; break; }
    }

    if (done) {
        g_best[t] = fmaxf(fminf(b0, b1), 0.0f);
    } else {
        int pos = atomicAdd(&g_ovfcnt, 1);   // rare tail queries
        g_ovf[pos] = t;
    }
}

// Warp-per-query brute force over the full opposing segment (8192 points).
__global__ void __launch_bounds__(256) brute_kernel() {
    const int cnt = g_ovfcnt;
    const int lane = threadIdx.x & 31;
    const int warp = (blockIdx.x * 256 + threadIdx.x) >> 5;   // 0..2047
    for (int j = warp; j < cnt; j += 2048) {
        const int t = g_ovf[j];
        const int dir = t >> 16;
        const int qi = t & 65535;
        const int b = qi >> 13, i = qi & 8191;
        const int qseg = b * 2 + dir;
        const int tseg = b * 2 + (1 - dir);

        float4 q = g_pts[qseg * PPS + i];
        const float nx = -q.x, ny = -q.y, nz = -q.z, qw = q.w;
        const float4* tp = g_pts + tseg * PPS;

        float best = CUDART_INF_F;
        for (int k = lane; k < PPS; k += 32) {
            float4 p = tp[k];
            float d = qw + p.w;
            d = fmaf(nx, p.x, d);
            d = fmaf(ny, p.y, d);
            d = fmaf(nz, p.z, d);
            best = fminf(best, d);
        }
#pragma unroll
        for (int o = 16; o >= 1; o >>= 1)
            best = fminf(best, __shfl_xor_sync(0xFFFFFFFFu, best, o));
        if (lane == 0) g_best[t] = fmaxf(best, 0.0f);
    }
}

// Single-block deterministic sum; also resets g_ovfcnt for the next call.
__global__ void final_kernel(float* __restrict__ out) {
    __shared__ float sred[1024];
    const int tid = threadIdx.x;
    float acc = 0.0f;
    const float4* p = reinterpret_cast<const float4*>(g_best);
#pragma unroll 8
    for (int i = tid; i < NQ / 4; i += 1024) {
        float4 v = p[i];
        acc += (v.x + v.y) + (v.z + v.w);
    }
    sred[tid] = acc;
    __syncthreads();
    for (int o = 512; o >= 1; o >>= 1) {
        if (tid < o) sred[tid] += sred[tid + o];
        __syncthreads();
    }
    if (tid == 0) {
        // d^2 = 2*d'; each direction is a mean over 65536 points.
        out[0] = sred[0] * (2.0f / 65536.0f);
        g_ovfcnt = 0;
    }
}

extern "C" void kernel_launch(void* const* d_in, const int* in_sizes, int n_in,
                              void* d_out, int out_size) {
    const float* gts   = (const float*)d_in[0];
    const float* preds = (const float*)d_in[1];
    float* out = (float*)d_out;

    count_kernel<<<512, 256>>>(gts, preds);
    scan1_kernel<<<SCAN_BLOCKS, 256>>>();
    scan3_kernel<<<SCAN_BLOCKS, 256>>>();
    scatter_kernel<<<512, 256>>>(gts, preds);
    query_kernel<<<512, 256>>>();
    brute_kernel<<<256, 256>>>();
    final_kernel<<<1, 1024>>>(out);
}